// round 3
// baseline (speedup 1.0000x reference)
#include <cuda_runtime.h>
#include <cuda_bf16.h>
#include <math_constants.h>
#include <cstdint>

// Problem constants
#define B_   16
#define S_   2048
#define D_   512
#define C_   8192

// GEMM tiling
#define BM 128
#define BN 128
#define BK 16
#define TM 8
#define TN 8
#define NTHREADS 256
#define SROW 20                 // floats per smem row (80B: 16 data + 4 pad)
#define ABUF (BM * SROW)        // floats per buffer per matrix (2560)

// 0.5 * ||embed[c]||^2
__device__ float g_e2h[C_];

__device__ __forceinline__ void cp_async16(unsigned int smem_addr, const void* gptr) {
    asm volatile("cp.async.cg.shared.global [%0], [%1], 16;\n"
                 :: "r"(smem_addr), "l"(gptr));
}
__device__ __forceinline__ void cp_commit() {
    asm volatile("cp.async.commit_group;\n");
}
__device__ __forceinline__ void cp_wait0() {
    asm volatile("cp.async.wait_group 0;\n");
}

// ---------------------------------------------------------------------------
// Kernel 1: e2h[c] = 0.5 * sum_d embed[c][d]^2
// ---------------------------------------------------------------------------
__global__ void e2_kernel(const float* __restrict__ embed) {
    int warp = threadIdx.x >> 5;
    int lane = threadIdx.x & 31;
    int c = blockIdx.x * 8 + warp;
    if (c >= C_) return;
    const float4* row = reinterpret_cast<const float4*>(embed + (size_t)c * D_);
    float s = 0.f;
    #pragma unroll
    for (int i = lane; i < D_ / 4; i += 32) {
        float4 v = row[i];
        s += v.x * v.x + v.y * v.y + v.z * v.z + v.w * v.w;
    }
    #pragma unroll
    for (int o = 16; o > 0; o >>= 1) s += __shfl_xor_sync(0xffffffffu, s, o);
    if (lane == 0) g_e2h[c] = 0.5f * s;
}

// ---------------------------------------------------------------------------
// Kernel 2: fused GEMM + streaming argmax + gather + mask
// Row-major smem tiles (dot-product micro-kernel), cp.async double buffer,
// 2 CTAs/SM.
// ---------------------------------------------------------------------------
__global__ void __launch_bounds__(NTHREADS, 2)
vq_kernel(const float* __restrict__ x,
          const int*   __restrict__ input_length,
          const float* __restrict__ embed,
          float*       __restrict__ out)
{
    // [As0 | As1 | Bs0 | Bs1], 40KB. Argmax arrays aliased on top afterwards.
    __shared__ __align__(16) float smem[4 * ABUF];
    __shared__ int sIdx[BM];

    const int tid   = threadIdx.x;
    const int bt    = blockIdx.x;
    const int TILES = S_ / BM;                 // 16
    const int batch = bt / TILES;
    const int tile  = bt % TILES;
    const int token0 = batch * S_ + tile * BM;

    const int len = input_length[batch];
    int active = len - tile * BM;
    active = active < 0 ? 0 : (active > BM ? BM : active);

    float* outq = out;                              // [B*S, D]
    float* outi = out + (size_t)B_ * S_ * D_;       // [B*S]

    if (active == 0) {
        float4 z = make_float4(0.f, 0.f, 0.f, 0.f);
        float4* q = reinterpret_cast<float4*>(outq + (size_t)token0 * D_);
        for (int i = tid; i < BM * (D_ / 4); i += NTHREADS) q[i] = z;
        if (tid < BM) outi[token0 + tid] = -1.0f;
        return;
    }

    const int ty = tid >> 4;        // 0..15 row group
    const int tx = tid & 15;        // 0..15 col group (codes tx + 16*j)

    // loader mapping: row = tid/2, 32B segment = (tid&1)*8 floats
    const int lrow = tid >> 1;
    const int lseg = (tid & 1) * 8;

    const unsigned int smem_base = (unsigned int)__cvta_generic_to_shared(smem);
    const unsigned int sA0 = smem_base;
    const unsigned int sB0 = smem_base + 2u * ABUF * 4u;
    const unsigned int sdst_off = (unsigned int)(lrow * SROW + lseg) * 4u;

    const float* xg = x + (size_t)(token0 + lrow) * D_ + lseg;

    float best_val[TM];
    int   best_idx[TM];
    #pragma unroll
    for (int i = 0; i < TM; i++) { best_val[i] = -CUDART_INF_F; best_idx[i] = 0; }

    const int NKB = D_ / BK;        // 32

    for (int c0 = 0; c0 < C_; c0 += BN) {
        const float* eg = embed + (size_t)(c0 + lrow) * D_ + lseg;

        // prologue: kb=0 into buffer 0
        {
            unsigned int da = sA0 + sdst_off;
            unsigned int db = sB0 + sdst_off;
            cp_async16(da,      xg);
            cp_async16(da + 16, xg + 4);
            cp_async16(db,      eg);
            cp_async16(db + 16, eg + 4);
            cp_commit();
        }

        float acc[TM][TN];
        #pragma unroll
        for (int i = 0; i < TM; i++)
            #pragma unroll
            for (int j = 0; j < TN; j++) acc[i][j] = 0.f;

        int p = 0;
        #pragma unroll 1
        for (int kb = 0; kb < NKB; ++kb) {
            cp_wait0();
            __syncthreads();

            if (kb + 1 < NKB) {
                int q = 1 - p;
                unsigned int da = sA0 + (unsigned int)(q * ABUF * 4) + sdst_off;
                unsigned int db = sB0 + (unsigned int)(q * ABUF * 4) + sdst_off;
                const float* xa = xg + (kb + 1) * BK;
                const float* ea = eg + (kb + 1) * BK;
                cp_async16(da,      xa);
                cp_async16(da + 16, xa + 4);
                cp_async16(db,      ea);
                cp_async16(db + 16, ea + 4);
                cp_commit();
            }

            const float* Ab = smem + p * ABUF;
            const float* Bb = smem + 2 * ABUF + p * ABUF;

            #pragma unroll
            for (int q4 = 0; q4 < BK / 4; q4++) {
                float4 av[TM];
                #pragma unroll
                for (int i = 0; i < TM; i++)
                    av[i] = *reinterpret_cast<const float4*>(Ab + (ty * TM + i) * SROW + q4 * 4);
                #pragma unroll
                for (int j = 0; j < TN; j++) {
                    float4 bv = *reinterpret_cast<const float4*>(Bb + (tx + 16 * j) * SROW + q4 * 4);
                    #pragma unroll
                    for (int i = 0; i < TM; i++) {
                        acc[i][j] = fmaf(av[i].x, bv.x, acc[i][j]);
                        acc[i][j] = fmaf(av[i].y, bv.y, acc[i][j]);
                        acc[i][j] = fmaf(av[i].z, bv.z, acc[i][j]);
                        acc[i][j] = fmaf(av[i].w, bv.w, acc[i][j]);
                    }
                }
            }
            p ^= 1;
        }

        // score = dot - 0.5||e||^2 ; codes strictly ascending within thread,
        // strict ">" keeps the lowest index on exact ties.
        #pragma unroll
        for (int j = 0; j < TN; j++) {
            int code = c0 + tx + 16 * j;
            float e2h = __ldg(&g_e2h[code]);
            #pragma unroll
            for (int i = 0; i < TM; i++) {
                float s = acc[i][j] - e2h;
                if (s > best_val[i]) { best_val[i] = s; best_idx[i] = code; }
            }
        }
    }

    // --- block-wide argmax reduction (alias argmax arrays over tile smem) ---
    __syncthreads();   // everyone done reading GEMM smem
    float* sVal = smem;                       // [BM][17]
    int*   sInd = (int*)(smem + BM * 17);     // [BM][17]

    #pragma unroll
    for (int i = 0; i < TM; i++) {
        sVal[(ty * TM + i) * 17 + tx] = best_val[i];
        sInd[(ty * TM + i) * 17 + tx] = best_idx[i];
    }
    __syncthreads();

    if (tid < BM) {
        float bv = sVal[tid * 17];
        int   bi = sInd[tid * 17];
        #pragma unroll
        for (int t = 1; t < 16; t++) {
            float v  = sVal[tid * 17 + t];
            int   ii = sInd[tid * 17 + t];
            if (v > bv || (v == bv && ii < bi)) { bv = v; bi = ii; }
        }
        sIdx[tid] = bi;
        outi[token0 + tid] = (tid < active) ? (float)bi : -1.0f;
    }
    __syncthreads();

    // --- gather embed[best] (zeros for masked rows) --------------------------
    float4* q = reinterpret_cast<float4*>(outq + (size_t)token0 * D_);
    const float4 z = make_float4(0.f, 0.f, 0.f, 0.f);
    for (int v = tid; v < BM * (D_ / 4); v += NTHREADS) {
        int r  = v >> 7;        // D_/4 = 128
        int dc = v & 127;
        float4 val = z;
        if (r < active) {
            val = reinterpret_cast<const float4*>(embed + (size_t)sIdx[r] * D_)[dc];
        }
        q[v] = val;
    }
}

// ---------------------------------------------------------------------------
extern "C" void kernel_launch(void* const* d_in, const int* in_sizes, int n_in,
                              void* d_out, int out_size)
{
    const float* x     = (const float*)d_in[0];
    const int*   ilen  = (const int*)  d_in[1];
    const float* embed = (const float*)d_in[2];
    float* out = (float*)d_out;

    e2_kernel<<<C_ / 8, 256>>>(embed);
    vq_kernel<<<(B_ * S_) / BM, NTHREADS>>>(x, ilen, embed, out);
}

// round 5
// speedup vs baseline: 4.9264x; 4.9264x over previous
#include <cuda_runtime.h>
#include <cuda_bf16.h>
#include <math_constants.h>
#include <cstdint>

// ---------------- problem constants ----------------
#define B_   16
#define S_   2048
#define D_   512
#define C_   8192
#define NTOK (B_*S_)

// ---------------- tiling ----------------
#define BM 128
#define BN 128
#define KS 64                     // K per slab
#define NKS (D_/KS)               // 8 slabs per chunk
#define NCH (C_/BN)               // 64 chunks
#define NSL (NCH*NKS)             // 512 slabs total
#define TILE16 16384              // one 128x64 bf16 tile (128B rows)
#define ST_B (4*TILE16)           // Ah, Al, Bh, Bl per stage = 64KB
#define DYN_SMEM (2*ST_B + 1024)
#define NTHREADS 256
#define NTILES (NTOK/BM)          // 256
#define GRID 148

// ---------------- device scratch ----------------
__device__ __nv_bfloat16 g_xh[NTOK*D_];
__device__ __nv_bfloat16 g_xl[NTOK*D_];
__device__ __nv_bfloat16 g_eh[C_*D_];
__device__ __nv_bfloat16 g_el[C_*D_];
__device__ float g_e2h[C_];
__device__ int   g_active[NTILES];
__device__ int   g_nactive;
__device__ int   g_counter;

// ---------------- helpers ----------------
__device__ __forceinline__ uint32_t smem_u32(const void* p) {
    uint32_t a;
    asm("{ .reg .u64 t; cvta.to.shared.u64 t, %1; cvt.u32.u64 %0, t; }" : "=r"(a) : "l"(p));
    return a;
}
__device__ __forceinline__ void cp_async16(uint32_t saddr, const void* gptr) {
    asm volatile("cp.async.cg.shared.global [%0], [%1], 16;\n" :: "r"(saddr), "l"(gptr));
}
__device__ __forceinline__ void cp_commit() { asm volatile("cp.async.commit_group;\n"); }
__device__ __forceinline__ void cp_wait0()  { asm volatile("cp.async.wait_group 0;\n" ::: "memory"); }

__device__ __forceinline__ void ldsm4(uint32_t* r, uint32_t addr) {
    asm volatile("ldmatrix.sync.aligned.m8n8.x4.shared.b16 {%0,%1,%2,%3}, [%4];"
                 : "=r"(r[0]), "=r"(r[1]), "=r"(r[2]), "=r"(r[3]) : "r"(addr));
}
__device__ __forceinline__ void mma_bf16(float* d, const uint32_t* a, const uint32_t* b) {
    asm("mma.sync.aligned.m16n8k16.row.col.f32.bf16.bf16.f32 "
        "{%0,%1,%2,%3}, {%4,%5,%6,%7}, {%8,%9}, {%0,%1,%2,%3};"
        : "+f"(d[0]), "+f"(d[1]), "+f"(d[2]), "+f"(d[3])
        : "r"(a[0]), "r"(a[1]), "r"(a[2]), "r"(a[3]), "r"(b[0]), "r"(b[1]));
}

__device__ __forceinline__ bool better(float a, int ia, float b, int ib) {
    return (a > b) || (a == b && ia < ib);
}
__device__ __forceinline__ void upd2(float& v1, int& i1, float& v2, int& i2, float s, int c) {
    if (better(s, c, v1, i1)) { v2 = v1; i2 = i1; v1 = s; i1 = c; }
    else if (better(s, c, v2, i2)) { v2 = s; i2 = c; }
}
__device__ __forceinline__ void merge2(float& v1, int& i1, float& v2, int& i2,
                                       float w1, int j1, float w2, int j2) {
    if (better(w1, j1, v1, i1)) {
        if (better(v1, i1, w2, j2)) { v2 = v1; i2 = i1; } else { v2 = w2; i2 = j2; }
        v1 = w1; i1 = j1;
    } else if (better(w1, j1, v2, i2)) { v2 = w1; i2 = j1; }
}

// ---------------- prep kernels ----------------
__global__ void split_bf16(const float* __restrict__ src,
                           __nv_bfloat16* __restrict__ hi,
                           __nv_bfloat16* __restrict__ lo, int n8) {
    int i = blockIdx.x * blockDim.x + threadIdx.x;
    if (i >= n8) return;
    const float4* s4 = reinterpret_cast<const float4*>(src);
    float4 v0 = s4[2 * i], v1 = s4[2 * i + 1];
    float vv[8] = {v0.x, v0.y, v0.z, v0.w, v1.x, v1.y, v1.z, v1.w};
    __align__(16) __nv_bfloat16 h[8];
    __align__(16) __nv_bfloat16 l[8];
    #pragma unroll
    for (int k = 0; k < 8; k++) {
        h[k] = __float2bfloat16(vv[k]);
        l[k] = __float2bfloat16(vv[k] - __bfloat162float(h[k]));
    }
    reinterpret_cast<uint4*>(hi)[i] = *reinterpret_cast<uint4*>(h);
    reinterpret_cast<uint4*>(lo)[i] = *reinterpret_cast<uint4*>(l);
}

__global__ void e2_kernel(const float* __restrict__ embed) {
    int warp = threadIdx.x >> 5, lane = threadIdx.x & 31;
    int c = blockIdx.x * 8 + warp;
    if (c >= C_) return;
    const float4* row = reinterpret_cast<const float4*>(embed + (size_t)c * D_);
    float s = 0.f;
    #pragma unroll
    for (int i = lane; i < D_ / 4; i += 32) {
        float4 v = row[i];
        s += v.x * v.x + v.y * v.y + v.z * v.z + v.w * v.w;
    }
    #pragma unroll
    for (int o = 16; o > 0; o >>= 1) s += __shfl_xor_sync(0xffffffffu, s, o);
    if (lane == 0) g_e2h[c] = 0.5f * s;
}

__global__ void build_active(const int* __restrict__ input_length) {
    __shared__ int cnt;
    int t = threadIdx.x;
    if (t == 0) { cnt = 0; g_counter = 0; }
    __syncthreads();
    int batch = t >> 4, tile = t & 15;
    int len = input_length[batch];
    int active = len - tile * BM;
    if (active > 0) { int p = atomicAdd(&cnt, 1); g_active[p] = t; }
    __syncthreads();
    if (t == 0) g_nactive = cnt;
}

__global__ void zero_kernel(const int* __restrict__ input_length, float* __restrict__ out) {
    int bt = blockIdx.x;
    int batch = bt >> 4, tile = bt & 15;
    int len = input_length[batch];
    if (len - tile * BM > 0) return;
    int token0 = batch * S_ + tile * BM;
    float* outi = out + (size_t)NTOK * D_;
    float4 z = make_float4(0.f, 0.f, 0.f, 0.f);
    float4* q = reinterpret_cast<float4*>(out + (size_t)token0 * D_);
    for (int i = threadIdx.x; i < BM * (D_ / 4); i += NTHREADS) q[i] = z;
    if (threadIdx.x < BM) outi[token0 + threadIdx.x] = -1.0f;
}

// ---------------- stage loader ----------------
__device__ __forceinline__ void stage_load(uint32_t sb, int tid, int token0, int c0, int koff) {
    #pragma unroll
    for (int rep = 0; rep < 4; rep++) {
        int idx = tid + rep * 256;
        int row = idx >> 3, ch = idx & 7;
        uint32_t off = (uint32_t)(row * 128) + (uint32_t)((ch ^ (row & 7)) << 4);
        size_t arow = (size_t)(token0 + row) * D_ + koff + ch * 8;
        size_t brow = (size_t)(c0 + row) * D_ + koff + ch * 8;
        cp_async16(sb + off,              g_xh + arow);
        cp_async16(sb + TILE16 + off,     g_xl + arow);
        cp_async16(sb + 2 * TILE16 + off, g_eh + brow);
        cp_async16(sb + 3 * TILE16 + off, g_el + brow);
    }
}

// ---------------- main fused kernel ----------------
__global__ void __launch_bounds__(NTHREADS, 1)
vq_mma_kernel(const float* __restrict__ x,
              const int*   __restrict__ input_length,
              const float* __restrict__ embed,
              float*       __restrict__ out)
{
    extern __shared__ char dsm[];
    __shared__ float4 red[2][BM];
    __shared__ float  se2[BN];
    __shared__ int    sIdx[BM];
    __shared__ int    s_job;

    const int tid    = threadIdx.x;
    const int wid    = tid >> 5;
    const int lane   = tid & 31;
    const int warp_m = wid & 3;
    const int warp_n = wid >> 2;
    const int g      = lane >> 2;
    const int tig    = lane & 3;

    const uint32_t dbase = (smem_u32(dsm) + 1023u) & ~1023u;

    // per-lane ldmatrix geometry
    const int arow_l   = (lane & 7) + (((lane >> 3) & 1) << 3);
    const int achunk_l = (lane >> 4);
    const int brow_l   = (lane & 7) + (((lane >> 4) & 1) << 3);
    const int bchunk_l = (lane >> 3) & 1;
    const int rmod     = lane & 7;

    uint32_t abase[2];
    #pragma unroll
    for (int mt = 0; mt < 2; mt++)
        abase[mt] = (uint32_t)((warp_m * 32 + mt * 16 + arow_l) * 128);
    uint32_t bbase[4];
    #pragma unroll
    for (int np = 0; np < 4; np++)
        bbase[np] = (uint32_t)((warp_n * 64 + np * 16 + brow_l) * 128);

    float* outq = out;
    float* outi = out + (size_t)NTOK * D_;

    while (true) {
        __syncthreads();
        if (tid == 0) s_job = atomicAdd(&g_counter, 1);
        __syncthreads();
        int job = s_job;
        if (job >= g_nactive) break;
        int bt = g_active[job];
        const int batch = bt >> 4, tile = bt & 15;
        const int token0 = batch * S_ + tile * BM;
        int len = input_length[batch];
        int active = len - tile * BM;
        active = active < 0 ? 0 : (active > BM ? BM : active);

        // running per-row top-2 (threads 0..127, row = tid)
        float rv1 = -CUDART_INF_F, rv2 = -CUDART_INF_F;
        int   ri1 = 0, ri2 = 0;

        // prologue
        stage_load(dbase, tid, token0, 0, 0);
        cp_commit();

        float acc[2][8][4];

        #pragma unroll 1
        for (int s = 0; s < NSL; s++) {
            const int c = s >> 3, ks = s & 7;
            cp_wait0();
            __syncthreads();
            if (s + 1 < NSL) {
                int s2 = s + 1;
                stage_load(dbase + (uint32_t)(s2 & 1) * ST_B, tid,
                           token0, (s2 >> 3) * BN, (s2 & 7) * KS);
                cp_commit();
            }
            if (ks == 0) {
                if (tid < BN) se2[tid] = g_e2h[c * BN + tid];
                #pragma unroll
                for (int mt = 0; mt < 2; mt++)
                    #pragma unroll
                    for (int nt = 0; nt < 8; nt++)
                        #pragma unroll
                        for (int r = 0; r < 4; r++) acc[mt][nt][r] = 0.f;
            }

            const uint32_t sb = dbase + (uint32_t)(s & 1) * ST_B;
            const uint32_t aH = sb, aL = sb + TILE16;
            const uint32_t bH = sb + 2 * TILE16, bL = sb + 3 * TILE16;

            #pragma unroll
            for (int kk = 0; kk < 4; kk++) {
                uint32_t ah[2][4], al[2][4];
                #pragma unroll
                for (int mt = 0; mt < 2; mt++) {
                    uint32_t off = abase[mt] + (uint32_t)((((kk * 2) + achunk_l) ^ rmod) << 4);
                    ldsm4(ah[mt], aH + off);
                    ldsm4(al[mt], aL + off);
                }
                #pragma unroll
                for (int np = 0; np < 4; np++) {
                    uint32_t off = bbase[np] + (uint32_t)((((kk * 2) + bchunk_l) ^ rmod) << 4);
                    uint32_t bh[4], bl[4];
                    ldsm4(bh, bH + off);
                    ldsm4(bl, bL + off);
                    #pragma unroll
                    for (int half = 0; half < 2; half++) {
                        const int nt = 2 * np + half;
                        #pragma unroll
                        for (int mt = 0; mt < 2; mt++) {
                            mma_bf16(acc[mt][nt], ah[mt], bh + 2 * half);
                            mma_bf16(acc[mt][nt], al[mt], bh + 2 * half);
                            mma_bf16(acc[mt][nt], ah[mt], bl + 2 * half);
                        }
                    }
                }
            }

            if (ks == 7) {
                // per-chunk argmax epilogue
                float tv1[4], tv2[4];
                int   ti1[4], ti2[4];
                #pragma unroll
                for (int sl = 0; sl < 4; sl++) {
                    tv1[sl] = -CUDART_INF_F; tv2[sl] = -CUDART_INF_F;
                    ti1[sl] = 0; ti2[sl] = 0;
                }
                #pragma unroll
                for (int nt = 0; nt < 8; nt++) {
                    int colb = warp_n * 64 + nt * 8 + tig * 2;
                    float e0 = se2[colb], e1 = se2[colb + 1];
                    int code0 = c * BN + colb;
                    #pragma unroll
                    for (int mt = 0; mt < 2; mt++) {
                        const float* d = acc[mt][nt];
                        upd2(tv1[2*mt], ti1[2*mt], tv2[2*mt], ti2[2*mt], d[0] - e0, code0);
                        upd2(tv1[2*mt], ti1[2*mt], tv2[2*mt], ti2[2*mt], d[1] - e1, code0 + 1);
                        upd2(tv1[2*mt+1], ti1[2*mt+1], tv2[2*mt+1], ti2[2*mt+1], d[2] - e0, code0);
                        upd2(tv1[2*mt+1], ti1[2*mt+1], tv2[2*mt+1], ti2[2*mt+1], d[3] - e1, code0 + 1);
                    }
                }
                #pragma unroll
                for (int off = 1; off < 4; off <<= 1) {
                    #pragma unroll
                    for (int sl = 0; sl < 4; sl++) {
                        float w1 = __shfl_xor_sync(0xffffffffu, tv1[sl], off);
                        int   j1 = __shfl_xor_sync(0xffffffffu, ti1[sl], off);
                        float w2 = __shfl_xor_sync(0xffffffffu, tv2[sl], off);
                        int   j2 = __shfl_xor_sync(0xffffffffu, ti2[sl], off);
                        merge2(tv1[sl], ti1[sl], tv2[sl], ti2[sl], w1, j1, w2, j2);
                    }
                }
                if (tig == 0) {
                    #pragma unroll
                    for (int sl = 0; sl < 4; sl++) {
                        int row = warp_m * 32 + (sl >> 1) * 16 + g + ((sl & 1) << 3);
                        red[warp_n][row] = make_float4(tv1[sl], __int_as_float(ti1[sl]),
                                                       tv2[sl], __int_as_float(ti2[sl]));
                    }
                }
                __syncthreads();
                if (tid < BM) {
                    float4 r0 = red[0][tid];
                    float4 r1 = red[1][tid];
                    merge2(rv1, ri1, rv2, ri2, r0.x, __float_as_int(r0.y), r0.z, __float_as_int(r0.w));
                    merge2(rv1, ri1, rv2, ri2, r1.x, __float_as_int(r1.y), r1.z, __float_as_int(r1.w));
                }
            }
        }
        __syncthreads();

        // ---- exact fp32 rescore of top-2 ----
        if (tid < BM) {
            int row = tid;
            int token = token0 + row;
            const float* xr  = x + (size_t)token * D_;
            const float* e1p = embed + (size_t)ri1 * D_;
            const float* e2p = embed + (size_t)ri2 * D_;
            float s1 = 0.f, s2 = 0.f;
            #pragma unroll 4
            for (int k = 0; k < D_; k += 4) {
                float4 xv = *reinterpret_cast<const float4*>(xr + k);
                float4 a  = *reinterpret_cast<const float4*>(e1p + k);
                float4 b  = *reinterpret_cast<const float4*>(e2p + k);
                s1 = fmaf(xv.x, a.x, s1); s1 = fmaf(xv.y, a.y, s1);
                s1 = fmaf(xv.z, a.z, s1); s1 = fmaf(xv.w, a.w, s1);
                s2 = fmaf(xv.x, b.x, s2); s2 = fmaf(xv.y, b.y, s2);
                s2 = fmaf(xv.z, b.z, s2); s2 = fmaf(xv.w, b.w, s2);
            }
            s1 -= __ldg(&g_e2h[ri1]);
            s2 -= __ldg(&g_e2h[ri2]);
            int best = better(s2, ri2, s1, ri1) ? ri2 : ri1;
            sIdx[row] = best;
            outi[token] = (row < active) ? (float)best : -1.0f;
        }
        __syncthreads();

        // ---- gather embed[best] (zeros for masked rows) ----
        float4* q = reinterpret_cast<float4*>(outq + (size_t)token0 * D_);
        const float4 z = make_float4(0.f, 0.f, 0.f, 0.f);
        for (int v = tid; v < BM * (D_ / 4); v += NTHREADS) {
            int r  = v >> 7;
            int dc = v & 127;
            float4 val = z;
            if (r < active)
                val = reinterpret_cast<const float4*>(embed + (size_t)sIdx[r] * D_)[dc];
            q[v] = val;
        }
    }
}

// ---------------------------------------------------------------------------
extern "C" void kernel_launch(void* const* d_in, const int* in_sizes, int n_in,
                              void* d_out, int out_size)
{
    const float* x     = (const float*)d_in[0];
    const int*   ilen  = (const int*)  d_in[1];
    const float* embed = (const float*)d_in[2];
    float* out = (float*)d_out;

    cudaFuncSetAttribute(vq_mma_kernel,
                         cudaFuncAttributeMaxDynamicSharedMemorySize, DYN_SMEM);

    __nv_bfloat16 *xh, *xl, *eh, *el;
    cudaGetSymbolAddress((void**)&xh, g_xh);
    cudaGetSymbolAddress((void**)&xl, g_xl);
    cudaGetSymbolAddress((void**)&eh, g_eh);
    cudaGetSymbolAddress((void**)&el, g_el);

    split_bf16<<<(NTOK * D_ / 8 + 255) / 256, 256>>>(x, xh, xl, NTOK * D_ / 8);
    split_bf16<<<(C_ * D_ / 8 + 255) / 256, 256>>>(embed, eh, el, C_ * D_ / 8);
    e2_kernel<<<C_ / 8, 256>>>(embed);
    build_active<<<1, NTILES>>>(ilen);
    zero_kernel<<<NTILES, NTHREADS>>>(ilen, out);
    vq_mma_kernel<<<GRID, NTHREADS, DYN_SMEM>>>(x, ilen, embed, out);
}